// round 1
// baseline (speedup 1.0000x reference)
#include <cuda_runtime.h>
#include <math.h>

#define K_BINS 30
#define NV     64
#define MINBW  1e-3f
#define MINBH  1e-3f
#define MIND   1e-3f
#define EPSB   1e-6f

// Per-variable spline tables, V-inner layout: table[k*NV + v].
__device__ float g_bounds[(K_BINS + 1) * NV];  // cumwidths, last entry += EPS (search array; icw for bin<=29)
__device__ float g_invw[K_BINS * NV];          // 1 / bin width
__device__ float g_cumh[(K_BINS + 1) * NV];    // cumheights
__device__ float g_h[K_BINS * NV];             // bin heights
__device__ float g_d[(K_BINS + 1) * NV];       // knot derivatives

// One thread per variable v; serial K=30 loops (trivial work, runs once).
__global__ void rqs_precompute(const float* __restrict__ uw,
                               const float* __restrict__ uh,
                               const float* __restrict__ ud) {
    int v = threadIdx.x;
    if (v >= NV) return;

    // ---- widths: softmax -> floor -> cumsum ----
    {
        float a[K_BINS];
        float m = -1e30f;
        #pragma unroll
        for (int k = 0; k < K_BINS; k++) { a[k] = uw[v * K_BINS + k]; m = fmaxf(m, a[k]); }
        float s = 0.f;
        #pragma unroll
        for (int k = 0; k < K_BINS; k++) { a[k] = expf(a[k] - m); s += a[k]; }
        float inv = 1.f / s;
        const float scale = 1.f - MINBW * (float)K_BINS;
        float cp = 0.f, prev = 0.f;
        g_bounds[v] = 0.f;
        #pragma unroll
        for (int k = 0; k < K_BINS; k++) {
            cp += MINBW + scale * (a[k] * inv);
            float c = (k == K_BINS - 1) ? 1.f : cp;                  // pin last knot to HI
            g_bounds[(k + 1) * NV + v] = (k == K_BINS - 1) ? (1.f + EPSB) : c;
            g_invw[k * NV + v] = 1.f / (c - prev);
            prev = c;
        }
    }
    // ---- heights ----
    {
        float a[K_BINS];
        float m = -1e30f;
        #pragma unroll
        for (int k = 0; k < K_BINS; k++) { a[k] = uh[v * K_BINS + k]; m = fmaxf(m, a[k]); }
        float s = 0.f;
        #pragma unroll
        for (int k = 0; k < K_BINS; k++) { a[k] = expf(a[k] - m); s += a[k]; }
        float inv = 1.f / s;
        const float scale = 1.f - MINBH * (float)K_BINS;
        float cp = 0.f, prev = 0.f;
        g_cumh[v] = 0.f;
        #pragma unroll
        for (int k = 0; k < K_BINS; k++) {
            cp += MINBH + scale * (a[k] * inv);
            float c = (k == K_BINS - 1) ? 1.f : cp;
            g_cumh[(k + 1) * NV + v] = c;
            g_h[k * NV + v] = c - prev;
            prev = c;
        }
    }
    // ---- derivatives: softplus with pinned boundary const ----
    {
        const float cst = logf(expf(1.f - MIND) - 1.f);
        #pragma unroll
        for (int k = 0; k <= K_BINS; k++) {
            float x = (k == 0 || k == K_BINS) ? cst : ud[v * (K_BINS - 1) + (k - 1)];
            float sp = (x > 20.f) ? x : log1pf(expf(x));
            g_d[k * NV + v] = MIND + sp;
        }
    }
}

__global__ void __launch_bounds__(256, 1)
rqs_main(const float4* __restrict__ in,
         float4* __restrict__ outv,
         float4* __restrict__ outl,
         int n4) {
    __shared__ float sB[(K_BINS + 1) * NV];
    __shared__ float sIW[K_BINS * NV];
    __shared__ float sCH[(K_BINS + 1) * NV];
    __shared__ float sH[K_BINS * NV];
    __shared__ float sD[(K_BINS + 1) * NV];

    for (int i = threadIdx.x; i < (K_BINS + 1) * NV; i += blockDim.x) {
        sB[i]  = g_bounds[i];
        sCH[i] = g_cumh[i];
        sD[i]  = g_d[i];
    }
    for (int i = threadIdx.x; i < K_BINS * NV; i += blockDim.x) {
        sIW[i] = g_invw[i];
        sH[i]  = g_h[i];
    }
    __syncthreads();

    const int stride = gridDim.x * blockDim.x;
    for (int t = blockIdx.x * blockDim.x + threadIdx.x; t < n4; t += stride) {
        float4 x4 = in[t];
        const int v0 = (t << 2) & (NV - 1);   // 64 % 4 == 0 -> no wrap within the float4
        float xin[4] = {x4.x, x4.y, x4.z, x4.w};
        float os[4], ls[4];

        #pragma unroll
        for (int j = 0; j < 4; j++) {
            const float x = xin[j];
            const int v = v0 + j;
            const float xc = fminf(fmaxf(x, 0.f), 1.f);

            // binary search over 31 monotone bounds (conflict-free: bank = v%32, distinct per lane)
            int lo = (xc >= sB[16 * NV + v]) ? 16 : 0;
            lo += (xc >= sB[(lo + 8) * NV + v]) ? 8 : 0;
            lo += (xc >= sB[(lo + 4) * NV + v]) ? 4 : 0;
            lo += (xc >= sB[(lo + 2) * NV + v]) ? 2 : 0;
            lo += (xc >= sB[(lo + 1) * NV + v]) ? 1 : 0;
            const int b = min(lo, K_BINS - 1);

            const float icw = sB[b * NV + v];         // cumw[b] (EPS only on index 30)
            const float iw  = sIW[b * NV + v];        // 1/width
            const float ich = sCH[b * NV + v];
            const float ih  = sH[b * NV + v];
            const float d0  = sD[b * NV + v];
            const float d1  = sD[(b + 1) * NV + v];

            const float idl   = ih * iw;              // delta = h/w
            const float theta = (xc - icw) * iw;
            const float omt   = 1.f - theta;
            const float t1mt  = theta * omt;
            const float th2   = theta * theta;

            const float num  = ih * fmaf(idl, th2, d0 * t1mt);
            const float den  = fmaf(d0 + d1 - 2.f * idl, t1mt, idl);
            const float rden = 1.f / den;
            const float so   = fmaf(num, rden, ich);

            const float dnum = idl * idl * fmaf(d1, th2, fmaf(2.f * idl, t1mt, d0 * omt * omt));
            const float sl   = __logf(dnum * rden * rden);   // log(dnum) - 2 log(den)

            const bool outside = (x < 0.f) || (x > 1.f);     // identity tails: slope 1 through (0,0),(1,1)
            os[j] = outside ? x : so;
            ls[j] = outside ? 0.f : sl;
        }
        outv[t] = make_float4(os[0], os[1], os[2], os[3]);
        outl[t] = make_float4(ls[0], ls[1], ls[2], ls[3]);
    }
}

extern "C" void kernel_launch(void* const* d_in, const int* in_sizes, int n_in,
                              void* d_out, int out_size) {
    const float* inputs = (const float*)d_in[0];
    const float* uw     = (const float*)d_in[1];
    const float* uh     = (const float*)d_in[2];
    const float* ud     = (const float*)d_in[3];
    float* out = (float*)d_out;

    const int n  = in_sizes[0];   // B*V elements
    const int n4 = n / 4;

    rqs_precompute<<<1, NV>>>(uw, uh, ud);
    // 148 SMs x 5 blocks (smem-limited: 5 x 39.2KB = 196KB/SM), grid-stride
    rqs_main<<<740, 256>>>((const float4*)inputs,
                           (float4*)out,
                           (float4*)(out + n),
                           n4);
}

// round 2
// speedup vs baseline: 1.6044x; 1.6044x over previous
#include <cuda_runtime.h>
#include <math.h>

#define K_BINS 30
#define NV     64
#define MINBW  1e-3f
#define MINBH  1e-3f
#define MIND   1e-3f
#define EPSB   1e-6f

// Packed per-variable tables, V-inner layout (index [k*NV + v]).
__device__ float4 g_P[K_BINS * NV];        // {cumw[b], 1/w[b], cumh[b], h[b]}
__device__ float  g_B[(K_BINS + 1) * NV];  // search bounds (cumw, last += EPS)
__device__ float  g_Dv[(K_BINS + 1) * NV]; // knot derivatives

// One warp per variable v: lanes = bins; shuffle reduce + inclusive scan.
__global__ void rqs_precompute(const float* __restrict__ uw,
                               const float* __restrict__ uh,
                               const float* __restrict__ ud) {
    const int v = blockIdx.x;
    const int lane = threadIdx.x;
    const unsigned FULL = 0xffffffffu;

    // ---------- widths ----------
    float aw = (lane < K_BINS) ? uw[v * K_BINS + lane] : -1e30f;
    float mw = aw;
    #pragma unroll
    for (int o = 16; o; o >>= 1) mw = fmaxf(mw, __shfl_xor_sync(FULL, mw, o));
    float ew = (lane < K_BINS) ? expf(aw - mw) : 0.f;
    float sw = ew;
    #pragma unroll
    for (int o = 16; o; o >>= 1) sw += __shfl_xor_sync(FULL, sw, o);
    float pw = MINBW + (1.f - MINBW * (float)K_BINS) * (ew / sw);
    float cw = pw;
    #pragma unroll
    for (int o = 1; o < 32; o <<= 1) {
        float t = __shfl_up_sync(FULL, cw, o);
        if (lane >= o) cw += t;
    }
    if (lane == K_BINS - 1) cw = 1.f;            // pin last knot
    float prevw = __shfl_up_sync(FULL, cw, 1);
    if (lane == 0) prevw = 0.f;

    // ---------- heights ----------
    float ah = (lane < K_BINS) ? uh[v * K_BINS + lane] : -1e30f;
    float mh = ah;
    #pragma unroll
    for (int o = 16; o; o >>= 1) mh = fmaxf(mh, __shfl_xor_sync(FULL, mh, o));
    float eh = (lane < K_BINS) ? expf(ah - mh) : 0.f;
    float sh = eh;
    #pragma unroll
    for (int o = 16; o; o >>= 1) sh += __shfl_xor_sync(FULL, sh, o);
    float ph = MINBH + (1.f - MINBH * (float)K_BINS) * (eh / sh);
    float ch = ph;
    #pragma unroll
    for (int o = 1; o < 32; o <<= 1) {
        float t = __shfl_up_sync(FULL, ch, o);
        if (lane >= o) ch += t;
    }
    if (lane == K_BINS - 1) ch = 1.f;
    float prevh = __shfl_up_sync(FULL, ch, 1);
    if (lane == 0) prevh = 0.f;

    if (lane < K_BINS) {
        g_B[(lane + 1) * NV + v] = (lane == K_BINS - 1) ? (1.f + EPSB) : cw;
        g_P[lane * NV + v] = make_float4(prevw, 1.f / (cw - prevw), prevh, ch - prevh);
    }
    if (lane == 0) g_B[v] = 0.f;

    // ---------- derivatives (lanes 0..30), boundary pinned ----------
    const float cst = logf(expf(1.f - MIND) - 1.f);
    float dx;
    if (lane == 0 || lane == K_BINS) dx = cst;
    else if (lane < K_BINS)          dx = ud[v * (K_BINS - 1) + (lane - 1)];
    else                             dx = 0.f;
    float sp = (dx > 20.f) ? dx : log1pf(expf(dx));
    if (lane <= K_BINS) g_Dv[lane * NV + v] = MIND + sp;
}

__global__ void __launch_bounds__(512, 4)
rqs_main(const float* __restrict__ in,
         float* __restrict__ outv,
         float* __restrict__ outl,
         int n) {
    __shared__ float4 sP[K_BINS * NV];            // 30 KB
    __shared__ float  sB[(K_BINS + 1) * NV];      // 7.75 KB
    __shared__ float  sD[(K_BINS + 1) * NV];      // 7.75 KB

    for (int i = threadIdx.x; i < K_BINS * NV; i += blockDim.x) sP[i] = g_P[i];
    for (int i = threadIdx.x; i < (K_BINS + 1) * NV; i += blockDim.x) {
        sB[i] = g_B[i];
        sD[i] = g_Dv[i];
    }
    __syncthreads();

    const int stride = gridDim.x * blockDim.x;
    for (int t = blockIdx.x * blockDim.x + threadIdx.x; t < n; t += stride) {
        const float x = in[t];
        const int v = t & (NV - 1);               // lanes cover 32 consecutive v -> all LDS conflict-free
        const float xc = fminf(fmaxf(x, 0.f), 1.f);

        // 5-step binary search over 31 monotone bounds
        int b = (xc >= sB[16 * NV + v]) ? 16 : 0;
        b += (xc >= sB[(b + 8) * NV + v]) ? 8 : 0;
        b += (xc >= sB[(b + 4) * NV + v]) ? 4 : 0;
        b += (xc >= sB[(b + 2) * NV + v]) ? 2 : 0;
        b += (xc >= sB[(b + 1) * NV + v]) ? 1 : 0;
        b = min(b, K_BINS - 1);

        const float4 P  = sP[b * NV + v];          // {cumw, invw, cumh, h}
        const float  d0 = sD[b * NV + v];
        const float  d1 = sD[(b + 1) * NV + v];

        const float idl   = P.w * P.y;             // delta = h/w
        const float theta = (xc - P.x) * P.y;
        const float omt   = 1.f - theta;
        const float t1mt  = theta * omt;
        const float th2   = theta * theta;

        const float num  = P.w * fmaf(idl, th2, d0 * t1mt);
        const float den  = fmaf(d0 + d1 - 2.f * idl, t1mt, idl);
        const float rden = __fdividef(1.f, den);
        const float so   = fmaf(num, rden, P.z);

        const float dnum = idl * idl * fmaf(d1, th2, fmaf(2.f * idl, t1mt, d0 * omt * omt));
        const float sl   = __logf(dnum * rden * rden);

        const bool outside = (x < 0.f) || (x > 1.f);   // identity tails
        outv[t] = outside ? x : so;
        outl[t] = outside ? 0.f : sl;
    }
}

extern "C" void kernel_launch(void* const* d_in, const int* in_sizes, int n_in,
                              void* d_out, int out_size) {
    const float* inputs = (const float*)d_in[0];
    const float* uw     = (const float*)d_in[1];
    const float* uh     = (const float*)d_in[2];
    const float* ud     = (const float*)d_in[3];
    float* out = (float*)d_out;

    const int n = in_sizes[0];  // B*V

    rqs_precompute<<<NV, 32>>>(uw, uh, ud);
    // 148 SMs x 4 blocks x 512 threads = full occupancy (smem 45.5KB/block, <=32 regs)
    rqs_main<<<592, 512>>>(inputs, out, out + n, n);
}

// round 3
// speedup vs baseline: 1.6222x; 1.0111x over previous
#include <cuda_runtime.h>
#include <math.h>

#define K_BINS 30
#define NV     64
#define MINBW  1e-3f
#define MINBH  1e-3f
#define MIND   1e-3f
#define EPSB   1e-6f

// Packed per-variable tables, V-inner layout (index [k*NV + v]).
__device__ float4 g_P[K_BINS * NV];        // {cumw[b], 1/w[b], cumh[b], h[b]}
__device__ float  g_B[32 * NV];            // search bounds: rows 0..29 cumw, row30 = 1+EPS, row31 = +inf pad
__device__ float  g_Dv[(K_BINS + 1) * NV]; // knot derivatives

// One warp per variable v: lanes = bins; shuffle reduce + inclusive scan.
__global__ void rqs_precompute(const float* __restrict__ uw,
                               const float* __restrict__ uh,
                               const float* __restrict__ ud) {
    const int v = blockIdx.x;
    const int lane = threadIdx.x;
    const unsigned FULL = 0xffffffffu;

    // ---------- widths ----------
    float aw = (lane < K_BINS) ? uw[v * K_BINS + lane] : -1e30f;
    float mw = aw;
    #pragma unroll
    for (int o = 16; o; o >>= 1) mw = fmaxf(mw, __shfl_xor_sync(FULL, mw, o));
    float ew = (lane < K_BINS) ? expf(aw - mw) : 0.f;
    float sw = ew;
    #pragma unroll
    for (int o = 16; o; o >>= 1) sw += __shfl_xor_sync(FULL, sw, o);
    float pw = MINBW + (1.f - MINBW * (float)K_BINS) * (ew / sw);
    float cw = pw;
    #pragma unroll
    for (int o = 1; o < 32; o <<= 1) {
        float t = __shfl_up_sync(FULL, cw, o);
        if (lane >= o) cw += t;
    }
    if (lane == K_BINS - 1) cw = 1.f;            // pin last knot
    float prevw = __shfl_up_sync(FULL, cw, 1);
    if (lane == 0) prevw = 0.f;

    // ---------- heights ----------
    float ah = (lane < K_BINS) ? uh[v * K_BINS + lane] : -1e30f;
    float mh = ah;
    #pragma unroll
    for (int o = 16; o; o >>= 1) mh = fmaxf(mh, __shfl_xor_sync(FULL, mh, o));
    float eh = (lane < K_BINS) ? expf(ah - mh) : 0.f;
    float sh = eh;
    #pragma unroll
    for (int o = 16; o; o >>= 1) sh += __shfl_xor_sync(FULL, sh, o);
    float ph = MINBH + (1.f - MINBH * (float)K_BINS) * (eh / sh);
    float ch = ph;
    #pragma unroll
    for (int o = 1; o < 32; o <<= 1) {
        float t = __shfl_up_sync(FULL, ch, o);
        if (lane >= o) ch += t;
    }
    if (lane == K_BINS - 1) ch = 1.f;
    float prevh = __shfl_up_sync(FULL, ch, 1);
    if (lane == 0) prevh = 0.f;

    if (lane < K_BINS) {
        g_B[(lane + 1) * NV + v] = (lane == K_BINS - 1) ? (1.f + EPSB) : cw;
        g_P[lane * NV + v] = make_float4(prevw, 1.f / (cw - prevw), prevh, ch - prevh);
    }
    if (lane == 0) {
        g_B[v] = 0.f;
        g_B[31 * NV + v] = 3.0e38f;              // +inf pad: fine search never selects it
    }

    // ---------- derivatives (lanes 0..30), boundary pinned ----------
    const float cst = logf(expf(1.f - MIND) - 1.f);
    float dx;
    if (lane == 0 || lane == K_BINS) dx = cst;
    else if (lane < K_BINS)          dx = ud[v * (K_BINS - 1) + (lane - 1)];
    else                             dx = 0.f;
    float sp = (dx > 20.f) ? dx : log1pf(expf(dx));
    if (lane <= K_BINS) g_Dv[lane * NV + v] = MIND + sp;
}

__global__ void __launch_bounds__(512, 4)
rqs_main(const float* __restrict__ in,
         float* __restrict__ outv,
         float* __restrict__ outl,
         int n) {
    __shared__ float4 sP[K_BINS * NV];            // 30 KB
    __shared__ float  sB[32 * NV];                // 8 KB (padded)
    __shared__ float  sD[(K_BINS + 1) * NV];      // 7.75 KB

    for (int i = threadIdx.x; i < K_BINS * NV; i += blockDim.x) sP[i] = g_P[i];
    for (int i = threadIdx.x; i < 32 * NV; i += blockDim.x) sB[i] = g_B[i];
    for (int i = threadIdx.x; i < (K_BINS + 1) * NV; i += blockDim.x) sD[i] = g_Dv[i];
    __syncthreads();

    const int tid0   = blockIdx.x * blockDim.x + threadIdx.x;
    const int stride = gridDim.x * blockDim.x;
    const int v      = tid0 & (NV - 1);           // loop-invariant: stride % 64 == 0

    for (int t = tid0; t < n; t += stride) {
        const float x  = in[t];
        const float xc = __saturatef(x);

        // depth-2 search: 7 parallel coarse compares (immediate offsets, conflict-free),
        // then 3 parallel fine compares. All table rows stride 64 -> bank = v%32 always.
        int c = (xc >= sB[ 4 * NV + v]);
        c += (xc >= sB[ 8 * NV + v]);
        c += (xc >= sB[12 * NV + v]);
        c += (xc >= sB[16 * NV + v]);
        c += (xc >= sB[20 * NV + v]);
        c += (xc >= sB[24 * NV + v]);
        c += (xc >= sB[28 * NV + v]);
        const int j  = c << 2;
        const int jb = j * NV + v;
        int b = j + (xc >= sB[jb + NV]) + (xc >= sB[jb + 2 * NV]) + (xc >= sB[jb + 3 * NV]);

        const float4 P  = sP[b * NV + v];          // {cumw, invw, cumh, h}
        const int    db = b * NV + v;
        const float  d0 = sD[db];
        const float  d1 = sD[db + NV];

        const float idl   = P.w * P.y;             // delta = h/w
        const float theta = (xc - P.x) * P.y;
        const float omt   = 1.f - theta;
        const float t1mt  = theta * omt;
        const float th2   = theta * theta;

        const float num  = P.w * fmaf(idl, th2, d0 * t1mt);
        const float den  = fmaf(d0 + d1 - 2.f * idl, t1mt, idl);
        const float rden = __fdividef(1.f, den);
        const float so   = fmaf(num, rden, P.z);

        const float dnum = idl * idl * fmaf(d1, th2, fmaf(2.f * idl, t1mt, d0 * omt * omt));
        const float sl   = __logf(dnum * rden * rden);

        const bool inside = (x == xc);             // identity tails outside [0,1]
        outv[t] = inside ? so : x;
        outl[t] = inside ? sl : 0.f;
    }
}

extern "C" void kernel_launch(void* const* d_in, const int* in_sizes, int n_in,
                              void* d_out, int out_size) {
    const float* inputs = (const float*)d_in[0];
    const float* uw     = (const float*)d_in[1];
    const float* uh     = (const float*)d_in[2];
    const float* ud     = (const float*)d_in[3];
    float* out = (float*)d_out;

    const int n = in_sizes[0];  // B*V

    rqs_precompute<<<NV, 32>>>(uw, uh, ud);
    // 148 SMs x 4 blocks x 512 threads (smem 45.75KB/block, <=32 regs)
    rqs_main<<<592, 512>>>(inputs, out, out + n, n);
}